// round 13
// baseline (speedup 1.0000x reference)
#include <cuda_runtime.h>
#include <cuda_fp16.h>
#include <math.h>
#include <stdint.h>

#define NVOX 40000
#define NQ   8192
#define KK   96
#define C    128
#define FF   256
#define NH   8
#define KVROW 136

// weight split buffer offsets (halfs)
#define W_INW  0
#define W_OUTW 49152
#define W_L1W  65536
#define W_L2W  98304
#define W_FINW 131072
#define W_TOT  147456

// prep kernel block ranges
#define PB_W   576
#define PB_KF  5000
#define PB_QF  4096
#define PB_TOT (PB_W + PB_KF + PB_QF)

// ---------------- scratch (device globals; no allocation) ----------------
__device__ __half g_w_hi[W_TOT],     g_w_lo[W_TOT];
__device__ __half g_kf_hi[NVOX * C];
__device__ __half g_KVh[NVOX * 2 * C];
__device__ __half g_qf_hi[NQ * C];
__device__ float  g_q[NQ * C];
__device__ __half g_ctx_hi[NQ * C],  g_ctx_lo[NQ * C];
__device__ float  g_att[NQ * C];
__device__ __half g_hn_hi[NQ * C],   g_hn_lo[NQ * C];
__device__ __half g_a1_hi[NQ * FF],  g_a1_lo[NQ * FF];
__device__ __half g_x_hi[NQ * C],    g_x_lo[NQ * C];

// ---------------- helpers ----------------
__device__ __forceinline__ void h2split(float x, __half& h, __half& l) {
    h = __float2half(x);
    l = __float2half(x - __half2float(h));
}

__device__ __forceinline__ int skey(int r) { return (r ^ (r >> 2)) & 3; }

__device__ __forceinline__ void ldsm4(uint32_t* r, uint32_t addr) {
    asm volatile("ldmatrix.sync.aligned.m8n8.x4.shared.b16 {%0,%1,%2,%3}, [%4];"
                 : "=r"(r[0]), "=r"(r[1]), "=r"(r[2]), "=r"(r[3]) : "r"(addr));
}

__device__ __forceinline__ void mma16(float* d, const uint32_t* a, const uint32_t* b) {
    asm volatile(
        "mma.sync.aligned.m16n8k16.row.col.f32.f16.f16.f32 "
        "{%0,%1,%2,%3}, {%4,%5,%6,%7}, {%8,%9}, {%0,%1,%2,%3};"
        : "+f"(d[0]), "+f"(d[1]), "+f"(d[2]), "+f"(d[3])
        : "r"(a[0]), "r"(a[1]), "r"(a[2]), "r"(a[3]), "r"(b[0]), "r"(b[1]));
}

__device__ __forceinline__ void cpa16(uint32_t s, const void* g) {
    asm volatile("cp.async.cg.shared.global [%0], [%1], 16;" :: "r"(s), "l"(g));
}
__device__ __forceinline__ void cpa_commit() {
    asm volatile("cp.async.commit_group;");
}
template <int N>
__device__ __forceinline__ void cpa_wait() {
    asm volatile("cp.async.wait_group %0;" :: "n"(N));
}

// ---------------- fused prep: weight split + kf (LN+pos) + qfeat -----------
__global__ __launch_bounds__(256)
void prep_kernel(const float* __restrict__ s0, const float* __restrict__ s1,
                 const float* __restrict__ s2, const float* __restrict__ s3,
                 const float* __restrict__ s4,
                 const float* __restrict__ vf, const float* __restrict__ vc,
                 const float* __restrict__ g1, const float* __restrict__ b1,
                 const float* __restrict__ kpw, const float* __restrict__ kpb,
                 const float* __restrict__ qc, const float* __restrict__ qpw,
                 const float* __restrict__ qpb)
{
    const int b = blockIdx.x;
    if (b < PB_W) {
        int i = b * 256 + threadIdx.x;
        const float* s; int off;
        if      (i < W_OUTW) { s = s0; off = W_INW;  }
        else if (i < W_L1W)  { s = s1; off = W_OUTW; }
        else if (i < W_L2W)  { s = s2; off = W_L1W;  }
        else if (i < W_FINW) { s = s3; off = W_L2W;  }
        else                 { s = s4; off = W_FINW; }
        __half h, l;
        h2split(s[i - off], h, l);
        g_w_hi[i] = h;
        g_w_lo[i] = l;
    } else if (b < PB_W + PB_KF) {
        int v    = (b - PB_W) * 8 + (threadIdx.x >> 5);
        int lane = threadIdx.x & 31;
        if (v >= NVOX) return;

        float4 x = ((const float4*)(vf + (size_t)v * C))[lane];
        float s = x.x + x.y + x.z + x.w;
        float q = x.x * x.x + x.y * x.y + x.z * x.z + x.w * x.w;
#pragma unroll
        for (int o = 16; o; o >>= 1) {
            s += __shfl_xor_sync(0xffffffffu, s, o);
            q += __shfl_xor_sync(0xffffffffu, q, o);
        }
        float m   = s * (1.0f / 128.0f);
        float var = q * (1.0f / 128.0f) - m * m;
        float r   = rsqrtf(var + 1e-5f);

        float cx = vc[v * 3 + 0], cy = vc[v * 3 + 1], cz = vc[v * 3 + 2];

        const float* xv = &x.x;
#pragma unroll
        for (int j = 0; j < 4; j++) {
            int c = lane * 4 + j;
            float y  = (xv[j] - m) * r * g1[c] + b1[c];
            float kp = fmaxf(kpw[c * 3 + 0] * cx + kpw[c * 3 + 1] * cy +
                             kpw[c * 3 + 2] * cz + kpb[c], 0.0f);
            g_kf_hi[v * C + c] = __float2half(y + kp);
        }
    } else {
        int t = (b - PB_W - PB_KF) * 256 + threadIdx.x;
        int n = t >> 7, c = t & 127;
        float x = qc[n * 3 + 0], y = qc[n * 3 + 1], z = qc[n * 3 + 2];
        float v = fmaxf(qpw[c * 3 + 0] * x + qpw[c * 3 + 1] * y +
                        qpw[c * 3 + 2] * z + qpb[c], 0.0f);
        g_qf_hi[t] = __float2half(v);
    }
}

// ---------------- row LayerNorm (norm2) -> half hi/lo ----------------
__global__ void ln_kernel(const float* __restrict__ in,
                          const float* __restrict__ g,
                          const float* __restrict__ b)
{
    int r    = blockIdx.x * 8 + (threadIdx.x >> 5);
    int lane = threadIdx.x & 31;

    float4 x = ((const float4*)(in + (size_t)r * C))[lane];
    float s = x.x + x.y + x.z + x.w;
    float q = x.x * x.x + x.y * x.y + x.z * x.z + x.w * x.w;
#pragma unroll
    for (int o = 16; o; o >>= 1) {
        s += __shfl_xor_sync(0xffffffffu, s, o);
        q += __shfl_xor_sync(0xffffffffu, q, o);
    }
    float m   = s * (1.0f / 128.0f);
    float var = q * (1.0f / 128.0f) - m * m;
    float rs  = rsqrtf(var + 1e-5f);

    const float* xv = &x.x;
#pragma unroll
    for (int j = 0; j < 4; j++) {
        int c = lane * 4 + j;
        __half h, l;
        h2split((xv[j] - m) * rs * g[c] + b[c], h, l);
        g_hn_hi[r * C + c] = h;
        g_hn_lo[r * C + c] = l;
    }
}

// ---------------- KV GEMM: 256 threads, CTA 128x128, fp16 single-pass -------
__global__ __launch_bounds__(256, 2)
void mma_kv(const __half* __restrict__ A, const __half* __restrict__ W,
            const float* __restrict__ bias, __half* __restrict__ outh,
            int M, int N, int Kd)
{
    __shared__ __align__(16) __half sA[2][128 * 32];
    __shared__ __align__(16) __half sB[2][128 * 32];

    const int tid  = threadIdx.x;
    const int m0   = blockIdx.x * 128;
    const int n0   = blockIdx.y * 128;
    const int lane = tid & 31;
    const int g    = lane >> 2;
    const int tig  = lane & 3;
    const int warp = tid >> 5;
    const int wm   = warp >> 1;
    const int wn   = warp & 1;

    const int lr = tid >> 2, lc = tid & 3;
    int so[2];
    bool okA[2];
#pragma unroll
    for (int i = 0; i < 2; i++) {
        int r = lr + 64 * i;
        so[i]  = (r * 32 + ((lc ^ skey(r)) << 3)) * 2;
        okA[i] = (m0 + r) < M;
    }

    uint32_t bA[2], bB[2];
#pragma unroll
    for (int bu = 0; bu < 2; bu++) {
        bA[bu] = (uint32_t)__cvta_generic_to_shared(sA[bu]);
        bB[bu] = (uint32_t)__cvta_generic_to_shared(sB[bu]);
    }

    const int mat = lane >> 3, l8 = lane & 7;
    int offA[2][2], offB[4][2];
#pragma unroll
    for (int kh = 0; kh < 2; kh++) {
#pragma unroll
        for (int i = 0; i < 2; i++) {
            int ra = wm * 32 + i * 16 + (mat & 1) * 8 + l8;
            int ca = kh * 2 + (mat >> 1);
            offA[i][kh] = (ra * 32 + ((ca ^ skey(ra)) << 3)) * 2;
        }
#pragma unroll
        for (int i = 0; i < 4; i++) {
            int rb = wn * 64 + i * 16 + (mat >> 1) * 8 + l8;
            int cb = kh * 2 + (mat & 1);
            offB[i][kh] = (rb * 32 + ((cb ^ skey(rb)) << 3)) * 2;
        }
    }

    float acc[2][8][4];
#pragma unroll
    for (int t = 0; t < 2; t++)
#pragma unroll
        for (int j = 0; j < 8; j++)
#pragma unroll
            for (int e = 0; e < 4; e++) acc[t][j][e] = 0.0f;

#pragma unroll
    for (int i = 0; i < 2; i++) {
        if (okA[i]) cpa16(bA[0] + so[i], A + (size_t)(m0 + lr + 64 * i) * Kd + lc * 8);
        cpa16(bB[0] + so[i], W + (size_t)(n0 + lr + 64 * i) * Kd + lc * 8);
    }
    cpa_commit();

    int buf = 0;
    for (int kc = 0; kc < Kd; kc += 32) {
        const bool more = (kc + 32) < Kd;
        if (more) {
            int nb = buf ^ 1;
            int ko = kc + 32;
#pragma unroll
            for (int i = 0; i < 2; i++) {
                if (okA[i]) cpa16(bA[nb] + so[i], A + (size_t)(m0 + lr + 64 * i) * Kd + ko + lc * 8);
                cpa16(bB[nb] + so[i], W + (size_t)(n0 + lr + 64 * i) * Kd + ko + lc * 8);
            }
            cpa_commit();
            cpa_wait<1>();
        } else {
            cpa_wait<0>();
        }
        __syncthreads();

#pragma unroll
        for (int kh = 0; kh < 2; kh++) {
            uint32_t ah[2][4], bh[4][4];
#pragma unroll
            for (int i = 0; i < 2; i++) ldsm4(ah[i], bA[buf] + offA[i][kh]);
#pragma unroll
            for (int i = 0; i < 4; i++) ldsm4(bh[i], bB[buf] + offB[i][kh]);
#pragma unroll
            for (int t = 0; t < 2; t++)
#pragma unroll
                for (int j = 0; j < 8; j++)
                    mma16(acc[t][j], ah[t], &bh[j >> 1][(j & 1) * 2]);
        }
        __syncthreads();
        buf ^= 1;
    }

#pragma unroll
    for (int t = 0; t < 2; t++) {
#pragma unroll
        for (int j = 0; j < 8; j++) {
            int row0 = m0 + wm * 32 + t * 16 + g;
            int col  = n0 + wn * 64 + j * 8 + 2 * tig;
            float2 bi = *(const float2*)(bias + col);
#pragma unroll
            for (int h2 = 0; h2 < 2; h2++) {
                int row = row0 + h2 * 8;
                if (row >= M) continue;
                float x0 = acc[t][j][h2 * 2 + 0] + bi.x;
                float x1 = acc[t][j][h2 * 2 + 1] + bi.y;
                *(__half2*)(outh + (size_t)row * N + col) = __floats2half2_rn(x0, x1);
            }
        }
    }
}

// ---------------- tensor-core GEMM (fp16, PL=1 single / PL=2 hi-lo x3) -----
template <int PL>
__global__ __launch_bounds__(128)
void mma_gemm(const __half* __restrict__ Ahi, const __half* __restrict__ Alo,
              const __half* __restrict__ Whi, const __half* __restrict__ Wlo,
              const float* __restrict__ bias, const float* __restrict__ res,
              float* __restrict__ out32, __half* __restrict__ outh,
              __half* __restrict__ ohi, __half* __restrict__ olo,
              int N, int Kd, int flags)
{
    __shared__ __align__(16) __half sA[2][PL][64 * 32];
    __shared__ __align__(16) __half sB[2][PL][64 * 32];

    const int tid  = threadIdx.x;
    const int m0   = blockIdx.x * 64;
    const int n0   = blockIdx.y * 64;
    const int lane = tid & 31;
    const int g    = lane >> 2;
    const int tig  = lane & 3;
    const int wm   = tid >> 6;
    const int wn   = (tid >> 5) & 1;

    const int lr0 = tid >> 2, lc = tid & 3, lr1 = lr0 + 32;
    const int so0 = (lr0 * 32 + ((lc ^ skey(lr0)) << 3)) * 2;
    const int so1 = (lr1 * 32 + ((lc ^ skey(lr1)) << 3)) * 2;

    uint32_t bA[2][PL], bB[2][PL];
#pragma unroll
    for (int bu = 0; bu < 2; bu++)
#pragma unroll
        for (int pl = 0; pl < PL; pl++) {
            bA[bu][pl] = (uint32_t)__cvta_generic_to_shared(sA[bu][pl]);
            bB[bu][pl] = (uint32_t)__cvta_generic_to_shared(sB[bu][pl]);
        }

    const int mat = lane >> 3, l8 = lane & 7;
    int offA[2][2], offB[2][2];
#pragma unroll
    for (int i = 0; i < 2; i++)
#pragma unroll
        for (int kh = 0; kh < 2; kh++) {
            int ra = wm * 32 + i * 16 + (mat & 1) * 8 + l8;
            int ca = kh * 2 + (mat >> 1);
            offA[i][kh] = (ra * 32 + ((ca ^ skey(ra)) << 3)) * 2;
            int rb = wn * 32 + i * 16 + (mat >> 1) * 8 + l8;
            int cb = kh * 2 + (mat & 1);
            offB[i][kh] = (rb * 32 + ((cb ^ skey(rb)) << 3)) * 2;
        }

    const __half* Ap[2] = { Ahi, Alo };
    const __half* Wp[2] = { Whi, Wlo };

    float acc[2][4][4];
#pragma unroll
    for (int t = 0; t < 2; t++)
#pragma unroll
        for (int j = 0; j < 4; j++)
#pragma unroll
            for (int e = 0; e < 4; e++) acc[t][j][e] = 0.0f;

#pragma unroll
    for (int pl = 0; pl < PL; pl++) {
        cpa16(bA[0][pl] + so0, Ap[pl] + (size_t)(m0 + lr0) * Kd + lc * 8);
        cpa16(bA[0][pl] + so1, Ap[pl] + (size_t)(m0 + lr1) * Kd + lc * 8);
        cpa16(bB[0][pl] + so0, Wp[pl] + (size_t)(n0 + lr0) * Kd + lc * 8);
        cpa16(bB[0][pl] + so1, Wp[pl] + (size_t)(n0 + lr1) * Kd + lc * 8);
    }
    cpa_commit();

    int buf = 0;
    for (int kc = 0; kc < Kd; kc += 32) {
        const bool more = (kc + 32) < Kd;
        if (more) {
            int nb = buf ^ 1;
            int ko = kc + 32;
#pragma unroll
            for (int pl = 0; pl < PL; pl++) {
                cpa16(bA[nb][pl] + so0, Ap[pl] + (size_t)(m0 + lr0) * Kd + ko + lc * 8);
                cpa16(bA[nb][pl] + so1, Ap[pl] + (size_t)(m0 + lr1) * Kd + ko + lc * 8);
                cpa16(bB[nb][pl] + so0, Wp[pl] + (size_t)(n0 + lr0) * Kd + ko + lc * 8);
                cpa16(bB[nb][pl] + so1, Wp[pl] + (size_t)(n0 + lr1) * Kd + ko + lc * 8);
            }
            cpa_commit();
            cpa_wait<1>();
        } else {
            cpa_wait<0>();
        }
        __syncthreads();

#pragma unroll
        for (int kh = 0; kh < 2; kh++) {
            uint32_t ah[2][4], bh[2][4];
            uint32_t al[2][4], bl[2][4];
#pragma unroll
            for (int i = 0; i < 2; i++) {
                ldsm4(ah[i], bA[buf][0] + offA[i][kh]);
                ldsm4(bh[i], bB[buf][0] + offB[i][kh]);
                if (PL == 2) {
                    ldsm4(al[i], bA[buf][1] + offA[i][kh]);
                    ldsm4(bl[i], bB[buf][1] + offB[i][kh]);
                }
            }
#pragma unroll
            for (int t = 0; t < 2; t++)
#pragma unroll
                for (int j = 0; j < 4; j++) {
                    const uint32_t* bhp = &bh[j >> 1][(j & 1) * 2];
                    mma16(acc[t][j], ah[t], bhp);
                    if (PL == 2) {
                        const uint32_t* blp = &bl[j >> 1][(j & 1) * 2];
                        mma16(acc[t][j], ah[t], blp);
                        mma16(acc[t][j], al[t], bhp);
                    }
                }
        }
        __syncthreads();
        buf ^= 1;
    }

#pragma unroll
    for (int t = 0; t < 2; t++) {
#pragma unroll
        for (int j = 0; j < 4; j++) {
            int row0 = m0 + wm * 32 + t * 16 + g;
            int col  = n0 + wn * 32 + j * 8 + 2 * tig;
            float2 bi = *(const float2*)(bias + col);
#pragma unroll
            for (int h2 = 0; h2 < 2; h2++) {
                int row = row0 + h2 * 8;
                float x0 = acc[t][j][h2 * 2 + 0] + bi.x;
                float x1 = acc[t][j][h2 * 2 + 1] + bi.y;
                size_t o = (size_t)row * N + col;
                if (flags & 2) {
                    float2 r2 = *(const float2*)(res + o);
                    x0 += r2.x; x1 += r2.y;
                }
                if (flags & 1) { x0 = fmaxf(x0, 0.0f); x1 = fmaxf(x1, 0.0f); }
                if (flags & 8)  *(float2*)(out32 + o) = make_float2(x0, x1);
                if (flags & 4)  *(__half2*)(outh + o) = __floats2half2_rn(x0, x1);
                if (flags & 16) {
                    __half h0, l0, h1, l1;
                    h2split(x0, h0, l0);
                    h2split(x1, h1, l1);
                    ohi[o] = h0; ohi[o + 1] = h1;
                    olo[o] = l0; olo[o + 1] = l1;
                }
            }
        }
    }
}

// ---------------- attention: one block per query, 128 threads ----------------
// K/V staged coalesced via smem; ctx uses key-split + vectorized V reads.
__global__ __launch_bounds__(128)
void attn_kernel(const int* __restrict__ kidx)
{
    __shared__ int   idx_s[KK];
    __shared__ float p_s[NH][KK];
    __shared__ __align__(16) __half kv_s[KK * KVROW];
    __shared__ float red_s[8][C];

    const int n = blockIdx.x;
    const int t = threadIdx.x;
    const int h = t >> 4, l16 = t & 15;

    if (t < KK) idx_s[t] = kidx[n * KK + t];
    __syncthreads();

    // ---- stage K rows coalesced: 16 threads per 256B row, 8 rows per pass ----
    const int rg = t >> 4;
    const int pp = t & 15;
#pragma unroll
    for (int i = 0; i < 12; i++) {
        int k = i * 8 + rg;
        int v = idx_s[k];
        uint4 d = make_uint4(0, 0, 0, 0);
        if (v >= 0) d = ((const uint4*)(g_KVh + (size_t)v * 256))[pp];
        *(uint4*)(&kv_s[k * KVROW + pp * 8]) = d;
    }

    float qreg[16];
    {
        const float* qp = g_q + (size_t)n * C + h * 16;
#pragma unroll
        for (int d = 0; d < 16; d++) qreg[d] = qp[d];
    }
    __syncthreads();

    // ---- scores from smem: thread (h,l16) handles keys k = l16 + 16m ----
    float sc[6];
#pragma unroll
    for (int m = 0; m < 6; m++) {
        int k = l16 + m * 16;
        uint4 r0 = *(const uint4*)&kv_s[k * KVROW + h * 16];
        uint4 r1 = *(const uint4*)&kv_s[k * KVROW + h * 16 + 8];
        const __half2* k0 = (const __half2*)&r0;
        const __half2* k1 = (const __half2*)&r1;
        float s = 0.0f;
#pragma unroll
        for (int d = 0; d < 4; d++) {
            float2 a = __half22float2(k0[d]);
            float2 b = __half22float2(k1[d]);
            s += qreg[2 * d] * a.x + qreg[2 * d + 1] * a.y;
            s += qreg[8 + 2 * d] * b.x + qreg[9 + 2 * d] * b.y;
        }
        sc[m] = s * 0.25f;
    }

    // ---- softmax over valid keys (width-16 reductions) ----
    int vmask[6];
#pragma unroll
    for (int m = 0; m < 6; m++) vmask[m] = idx_s[l16 + m * 16];

    float mx = -1e30f;
#pragma unroll
    for (int m = 0; m < 6; m++)
        if (vmask[m] >= 0) mx = fmaxf(mx, sc[m]);
#pragma unroll
    for (int o = 8; o; o >>= 1)
        mx = fmaxf(mx, __shfl_xor_sync(0xffffffffu, mx, o, 16));

    float p[6];
    float sum = 0.0f;
#pragma unroll
    for (int m = 0; m < 6; m++) {
        p[m] = (vmask[m] >= 0) ? __expf(sc[m] - mx) : 0.0f;
        sum += p[m];
    }
#pragma unroll
    for (int o = 8; o; o >>= 1)
        sum += __shfl_xor_sync(0xffffffffu, sum, o, 16);
    const float inv = 1.0f / sum;
#pragma unroll
    for (int m = 0; m < 6; m++) p_s[h][l16 + m * 16] = p[m] * inv;
    __syncthreads();

    // ---- stage V rows (second 256B half of each KV row) ----
#pragma unroll
    for (int i = 0; i < 12; i++) {
        int k = i * 8 + rg;
        int v = idx_s[k];
        uint4 d = make_uint4(0, 0, 0, 0);
        if (v >= 0) d = ((const uint4*)(g_KVh + (size_t)v * 256))[16 + pp];
        *(uint4*)(&kv_s[k * KVROW + pp * 8]) = d;
    }
    __syncthreads();

    // ---- ctx: key-split. thread (kg = t>>4, cb = t&15):
    //      accumulates keys kg*12..+11 for channels cb*8..cb*8+7 ----
    {
        const int kg  = t >> 4;      // 0..7 key group
        const int cb  = t & 15;      // 8-channel block
        const int hh2 = cb >> 1;     // head of these channels
        float facc[8];
#pragma unroll
        for (int j = 0; j < 8; j++) facc[j] = 0.0f;
#pragma unroll
        for (int i = 0; i < 12; i++) {
            int k = kg * 12 + i;
            float pk = p_s[hh2][k];
            uint4 v4 = *(const uint4*)&kv_s[k * KVROW + cb * 8];
            const __half2* vh = (const __half2*)&v4;
#pragma unroll
            for (int j = 0; j < 4; j++) {
                float2 f = __half22float2(vh[j]);
                facc[2 * j + 0] += pk * f.x;
                facc[2 * j + 1] += pk * f.y;
            }
        }
        *(float4*)&red_s[kg][cb * 8]     = make_float4(facc[0], facc[1], facc[2], facc[3]);
        *(float4*)&red_s[kg][cb * 8 + 4] = make_float4(facc[4], facc[5], facc[6], facc[7]);
    }
    __syncthreads();

    float acc = 0.0f;
#pragma unroll
    for (int kg2 = 0; kg2 < 8; kg2++) acc += red_s[kg2][t];

    __half hh, ll;
    h2split(acc, hh, ll);
    g_ctx_hi[n * C + t] = hh;
    g_ctx_lo[n * C + t] = ll;
}

// ---------------- host launch ----------------
extern "C" void kernel_launch(void* const* d_in, const int* in_sizes, int n_in,
                              void* d_out, int out_size)
{
    const float* vf   = (const float*)d_in[0];
    const float* vc   = (const float*)d_in[1];
    const float* qc   = (const float*)d_in[2];
    const int*   kidx = (const int*)  d_in[3];
    const float* n1g  = (const float*)d_in[4];
    const float* n1b  = (const float*)d_in[5];
    const float* qpw  = (const float*)d_in[6];
    const float* qpb  = (const float*)d_in[7];
    const float* kpw  = (const float*)d_in[8];
    const float* kpb  = (const float*)d_in[9];
    const float* inw  = (const float*)d_in[10];
    const float* inb  = (const float*)d_in[11];
    const float* outw = (const float*)d_in[12];
    const float* outb = (const float*)d_in[13];
    const float* n2g  = (const float*)d_in[14];
    const float* n2b  = (const float*)d_in[15];
    const float* l1w  = (const float*)d_in[16];
    const float* l1b  = (const float*)d_in[17];
    const float* l2w  = (const float*)d_in[18];
    const float* l2b  = (const float*)d_in[19];
    const float* fw   = (const float*)d_in[20];
    const float* fb   = (const float*)d_in[21];
    float* out = (float*)d_out;

    __half *p_kf_hi, *p_qf_hi, *p_ctx_hi, *p_ctx_lo;
    __half *p_hn_hi, *p_hn_lo, *p_a1_hi, *p_a1_lo, *p_x_hi, *p_x_lo;
    __half *p_w_hi, *p_w_lo, *p_KVh;
    float *p_q, *p_att;
    cudaGetSymbolAddress((void**)&p_kf_hi,  g_kf_hi);
    cudaGetSymbolAddress((void**)&p_KVh,    g_KVh);
    cudaGetSymbolAddress((void**)&p_qf_hi,  g_qf_hi);
    cudaGetSymbolAddress((void**)&p_q,      g_q);
    cudaGetSymbolAddress((void**)&p_ctx_hi, g_ctx_hi);
    cudaGetSymbolAddress((void**)&p_ctx_lo, g_ctx_lo);
    cudaGetSymbolAddress((void**)&p_att,    g_att);
    cudaGetSymbolAddress((void**)&p_hn_hi,  g_hn_hi);
    cudaGetSymbolAddress((void**)&p_hn_lo,  g_hn_lo);
    cudaGetSymbolAddress((void**)&p_a1_hi,  g_a1_hi);
    cudaGetSymbolAddress((void**)&p_a1_lo,  g_a1_lo);
    cudaGetSymbolAddress((void**)&p_x_hi,   g_x_hi);
    cudaGetSymbolAddress((void**)&p_x_lo,   g_x_lo);
    cudaGetSymbolAddress((void**)&p_w_hi,   g_w_hi);
    cudaGetSymbolAddress((void**)&p_w_lo,   g_w_lo);

    // 0) fused prep: weight split + kf + qfeat
    prep_kernel<<<PB_TOT, 256>>>(inw, outw, l1w, l2w, fw,
                                 vf, vc, n1g, n1b, kpw, kpb,
                                 qc, qpw, qpb);

    // 1) per-voxel K|V projection (fp16, 128x128 tile, 256 thr) -> fp16
    mma_kv<<<dim3((NVOX + 127) / 128, 2), 256>>>(
        p_kf_hi, p_w_hi + W_INW + 128 * 128, inb + 128, p_KVh,
        NVOX, 256, 128);

    // 2) q projection (single-pass fp16) -> fp32
    mma_gemm<1><<<dim3(NQ / 64, 2), 128>>>(
        p_qf_hi, nullptr, p_w_hi + W_INW, nullptr,
        inb, nullptr, p_q, nullptr, nullptr, nullptr, 128, 128, 8);

    // 3) sparse attention -> ctx hi/lo
    attn_kernel<<<NQ, 128>>>(kidx);

    // 4) output projection (3-pass) -> attend fp32
    mma_gemm<2><<<dim3(NQ / 64, 2), 128>>>(
        p_ctx_hi, p_ctx_lo, p_w_hi + W_OUTW, p_w_lo + W_OUTW,
        outb, nullptr, p_att, nullptr, nullptr, nullptr, 128, 128, 8);

    // 5) norm2 -> hn hi/lo
    ln_kernel<<<NQ / 8, 256>>>(p_att, n2g, n2b);

    // 6) FFN up (relu, 3-pass) -> a1 hi/lo
    mma_gemm<2><<<dim3(NQ / 64, 4), 128>>>(
        p_hn_hi, p_hn_lo, p_w_hi + W_L1W, p_w_lo + W_L1W,
        l1b, nullptr, nullptr, nullptr, p_a1_hi, p_a1_lo, 256, 128, 16 | 1);

    // 7) FFN down + residual(attend) (3-pass) -> x hi/lo
    mma_gemm<2><<<dim3(NQ / 64, 2), 128>>>(
        p_a1_hi, p_a1_lo, p_w_hi + W_L2W, p_w_lo + W_L2W,
        l2b, p_att, nullptr, nullptr, p_x_hi, p_x_lo, 128, 256, 16 | 2);

    // 8) final projection + relu (3-pass) -> output fp32
    mma_gemm<2><<<dim3(NQ / 64, 2), 128>>>(
        p_x_hi, p_x_lo, p_w_hi + W_FINW, p_w_lo + W_FINW,
        fb, nullptr, out, nullptr, nullptr, nullptr, 128, 128, 8 | 1);
}

// round 14
// speedup vs baseline: 1.3302x; 1.3302x over previous
#include <cuda_runtime.h>
#include <cuda_fp16.h>
#include <math.h>
#include <stdint.h>

#define NVOX 40000
#define NQ   8192
#define KK   96
#define C    128
#define FF   256
#define NH   8
#define PSS  100   // padded p_s row stride (floats) -> conflict-free ctx reads

// weight split buffer offsets (halfs)
#define W_INW  0
#define W_OUTW 49152
#define W_L1W  65536
#define W_L2W  98304
#define W_FINW 131072
#define W_TOT  147456

// prep kernel block ranges
#define PB_W   576
#define PB_KF  5000
#define PB_QF  4096
#define PB_TOT (PB_W + PB_KF + PB_QF)

// ---------------- scratch (device globals; no allocation) ----------------
__device__ __half g_w_hi[W_TOT],     g_w_lo[W_TOT];
__device__ __half g_kf_hi[NVOX * C];
__device__ __half g_KVh[NVOX * 2 * C];
__device__ __half g_qf_hi[NQ * C];
__device__ float  g_q[NQ * C];
__device__ __half g_ctx_hi[NQ * C],  g_ctx_lo[NQ * C];
__device__ float  g_att[NQ * C];
__device__ __half g_hn_hi[NQ * C],   g_hn_lo[NQ * C];
__device__ __half g_a1_hi[NQ * FF],  g_a1_lo[NQ * FF];
__device__ __half g_x_hi[NQ * C],    g_x_lo[NQ * C];

// ---------------- helpers ----------------
__device__ __forceinline__ void h2split(float x, __half& h, __half& l) {
    h = __float2half(x);
    l = __float2half(x - __half2float(h));
}

__device__ __forceinline__ int skey(int r) { return (r ^ (r >> 2)) & 3; }

__device__ __forceinline__ void ldsm4(uint32_t* r, uint32_t addr) {
    asm volatile("ldmatrix.sync.aligned.m8n8.x4.shared.b16 {%0,%1,%2,%3}, [%4];"
                 : "=r"(r[0]), "=r"(r[1]), "=r"(r[2]), "=r"(r[3]) : "r"(addr));
}

__device__ __forceinline__ void mma16(float* d, const uint32_t* a, const uint32_t* b) {
    asm volatile(
        "mma.sync.aligned.m16n8k16.row.col.f32.f16.f16.f32 "
        "{%0,%1,%2,%3}, {%4,%5,%6,%7}, {%8,%9}, {%0,%1,%2,%3};"
        : "+f"(d[0]), "+f"(d[1]), "+f"(d[2]), "+f"(d[3])
        : "r"(a[0]), "r"(a[1]), "r"(a[2]), "r"(a[3]), "r"(b[0]), "r"(b[1]));
}

__device__ __forceinline__ void cpa16(uint32_t s, const void* g) {
    asm volatile("cp.async.cg.shared.global [%0], [%1], 16;" :: "r"(s), "l"(g));
}
__device__ __forceinline__ void cpa_commit() {
    asm volatile("cp.async.commit_group;");
}
template <int N>
__device__ __forceinline__ void cpa_wait() {
    asm volatile("cp.async.wait_group %0;" :: "n"(N));
}

// ---------------- fused prep: weight split + kf (LN+pos) + qfeat -----------
__global__ __launch_bounds__(256)
void prep_kernel(const float* __restrict__ s0, const float* __restrict__ s1,
                 const float* __restrict__ s2, const float* __restrict__ s3,
                 const float* __restrict__ s4,
                 const float* __restrict__ vf, const float* __restrict__ vc,
                 const float* __restrict__ g1, const float* __restrict__ b1,
                 const float* __restrict__ kpw, const float* __restrict__ kpb,
                 const float* __restrict__ qc, const float* __restrict__ qpw,
                 const float* __restrict__ qpb)
{
    const int b = blockIdx.x;
    if (b < PB_W) {
        int i = b * 256 + threadIdx.x;
        const float* s; int off;
        if      (i < W_OUTW) { s = s0; off = W_INW;  }
        else if (i < W_L1W)  { s = s1; off = W_OUTW; }
        else if (i < W_L2W)  { s = s2; off = W_L1W;  }
        else if (i < W_FINW) { s = s3; off = W_L2W;  }
        else                 { s = s4; off = W_FINW; }
        __half h, l;
        h2split(s[i - off], h, l);
        g_w_hi[i] = h;
        g_w_lo[i] = l;
    } else if (b < PB_W + PB_KF) {
        int v    = (b - PB_W) * 8 + (threadIdx.x >> 5);
        int lane = threadIdx.x & 31;
        if (v >= NVOX) return;

        float4 x = ((const float4*)(vf + (size_t)v * C))[lane];
        float s = x.x + x.y + x.z + x.w;
        float q = x.x * x.x + x.y * x.y + x.z * x.z + x.w * x.w;
#pragma unroll
        for (int o = 16; o; o >>= 1) {
            s += __shfl_xor_sync(0xffffffffu, s, o);
            q += __shfl_xor_sync(0xffffffffu, q, o);
        }
        float m   = s * (1.0f / 128.0f);
        float var = q * (1.0f / 128.0f) - m * m;
        float r   = rsqrtf(var + 1e-5f);

        float cx = vc[v * 3 + 0], cy = vc[v * 3 + 1], cz = vc[v * 3 + 2];

        const float* xv = &x.x;
#pragma unroll
        for (int j = 0; j < 4; j++) {
            int c = lane * 4 + j;
            float y  = (xv[j] - m) * r * g1[c] + b1[c];
            float kp = fmaxf(kpw[c * 3 + 0] * cx + kpw[c * 3 + 1] * cy +
                             kpw[c * 3 + 2] * cz + kpb[c], 0.0f);
            g_kf_hi[v * C + c] = __float2half(y + kp);
        }
    } else {
        int t = (b - PB_W - PB_KF) * 256 + threadIdx.x;
        int n = t >> 7, c = t & 127;
        float x = qc[n * 3 + 0], y = qc[n * 3 + 1], z = qc[n * 3 + 2];
        float v = fmaxf(qpw[c * 3 + 0] * x + qpw[c * 3 + 1] * y +
                        qpw[c * 3 + 2] * z + qpb[c], 0.0f);
        g_qf_hi[t] = __float2half(v);
    }
}

// ---------------- row LayerNorm (norm2) -> half hi/lo ----------------
__global__ void ln_kernel(const float* __restrict__ in,
                          const float* __restrict__ g,
                          const float* __restrict__ b)
{
    int r    = blockIdx.x * 8 + (threadIdx.x >> 5);
    int lane = threadIdx.x & 31;

    float4 x = ((const float4*)(in + (size_t)r * C))[lane];
    float s = x.x + x.y + x.z + x.w;
    float q = x.x * x.x + x.y * x.y + x.z * x.z + x.w * x.w;
#pragma unroll
    for (int o = 16; o; o >>= 1) {
        s += __shfl_xor_sync(0xffffffffu, s, o);
        q += __shfl_xor_sync(0xffffffffu, q, o);
    }
    float m   = s * (1.0f / 128.0f);
    float var = q * (1.0f / 128.0f) - m * m;
    float rs  = rsqrtf(var + 1e-5f);

    const float* xv = &x.x;
#pragma unroll
    for (int j = 0; j < 4; j++) {
        int c = lane * 4 + j;
        __half h, l;
        h2split((xv[j] - m) * rs * g[c] + b[c], h, l);
        g_hn_hi[r * C + c] = h;
        g_hn_lo[r * C + c] = l;
    }
}

// ---------------- KV GEMM: 256 threads, CTA 128x128, fp16 single-pass -------
__global__ __launch_bounds__(256, 2)
void mma_kv(const __half* __restrict__ A, const __half* __restrict__ W,
            const float* __restrict__ bias, __half* __restrict__ outh,
            int M, int N, int Kd)
{
    __shared__ __align__(16) __half sA[2][128 * 32];
    __shared__ __align__(16) __half sB[2][128 * 32];

    const int tid  = threadIdx.x;
    const int m0   = blockIdx.x * 128;
    const int n0   = blockIdx.y * 128;
    const int lane = tid & 31;
    const int g    = lane >> 2;
    const int tig  = lane & 3;
    const int warp = tid >> 5;
    const int wm   = warp >> 1;
    const int wn   = warp & 1;

    const int lr = tid >> 2, lc = tid & 3;
    int so[2];
    bool okA[2];
#pragma unroll
    for (int i = 0; i < 2; i++) {
        int r = lr + 64 * i;
        so[i]  = (r * 32 + ((lc ^ skey(r)) << 3)) * 2;
        okA[i] = (m0 + r) < M;
    }

    uint32_t bA[2], bB[2];
#pragma unroll
    for (int bu = 0; bu < 2; bu++) {
        bA[bu] = (uint32_t)__cvta_generic_to_shared(sA[bu]);
        bB[bu] = (uint32_t)__cvta_generic_to_shared(sB[bu]);
    }

    const int mat = lane >> 3, l8 = lane & 7;
    int offA[2][2], offB[4][2];
#pragma unroll
    for (int kh = 0; kh < 2; kh++) {
#pragma unroll
        for (int i = 0; i < 2; i++) {
            int ra = wm * 32 + i * 16 + (mat & 1) * 8 + l8;
            int ca = kh * 2 + (mat >> 1);
            offA[i][kh] = (ra * 32 + ((ca ^ skey(ra)) << 3)) * 2;
        }
#pragma unroll
        for (int i = 0; i < 4; i++) {
            int rb = wn * 64 + i * 16 + (mat >> 1) * 8 + l8;
            int cb = kh * 2 + (mat & 1);
            offB[i][kh] = (rb * 32 + ((cb ^ skey(rb)) << 3)) * 2;
        }
    }

    float acc[2][8][4];
#pragma unroll
    for (int t = 0; t < 2; t++)
#pragma unroll
        for (int j = 0; j < 8; j++)
#pragma unroll
            for (int e = 0; e < 4; e++) acc[t][j][e] = 0.0f;

#pragma unroll
    for (int i = 0; i < 2; i++) {
        if (okA[i]) cpa16(bA[0] + so[i], A + (size_t)(m0 + lr + 64 * i) * Kd + lc * 8);
        cpa16(bB[0] + so[i], W + (size_t)(n0 + lr + 64 * i) * Kd + lc * 8);
    }
    cpa_commit();

    int buf = 0;
    for (int kc = 0; kc < Kd; kc += 32) {
        const bool more = (kc + 32) < Kd;
        if (more) {
            int nb = buf ^ 1;
            int ko = kc + 32;
#pragma unroll
            for (int i = 0; i < 2; i++) {
                if (okA[i]) cpa16(bA[nb] + so[i], A + (size_t)(m0 + lr + 64 * i) * Kd + ko + lc * 8);
                cpa16(bB[nb] + so[i], W + (size_t)(n0 + lr + 64 * i) * Kd + ko + lc * 8);
            }
            cpa_commit();
            cpa_wait<1>();
        } else {
            cpa_wait<0>();
        }
        __syncthreads();

#pragma unroll
        for (int kh = 0; kh < 2; kh++) {
            uint32_t ah[2][4], bh[4][4];
#pragma unroll
            for (int i = 0; i < 2; i++) ldsm4(ah[i], bA[buf] + offA[i][kh]);
#pragma unroll
            for (int i = 0; i < 4; i++) ldsm4(bh[i], bB[buf] + offB[i][kh]);
#pragma unroll
            for (int t = 0; t < 2; t++)
#pragma unroll
                for (int j = 0; j < 8; j++)
                    mma16(acc[t][j], ah[t], &bh[j >> 1][(j & 1) * 2]);
        }
        __syncthreads();
        buf ^= 1;
    }

#pragma unroll
    for (int t = 0; t < 2; t++) {
#pragma unroll
        for (int j = 0; j < 8; j++) {
            int row0 = m0 + wm * 32 + t * 16 + g;
            int col  = n0 + wn * 64 + j * 8 + 2 * tig;
            float2 bi = *(const float2*)(bias + col);
#pragma unroll
            for (int h2 = 0; h2 < 2; h2++) {
                int row = row0 + h2 * 8;
                if (row >= M) continue;
                float x0 = acc[t][j][h2 * 2 + 0] + bi.x;
                float x1 = acc[t][j][h2 * 2 + 1] + bi.y;
                *(__half2*)(outh + (size_t)row * N + col) = __floats2half2_rn(x0, x1);
            }
        }
    }
}

// ---------------- tensor-core GEMM (fp16, PL=1 single / PL=2 hi-lo x3) -----
template <int PL>
__global__ __launch_bounds__(128)
void mma_gemm(const __half* __restrict__ Ahi, const __half* __restrict__ Alo,
              const __half* __restrict__ Whi, const __half* __restrict__ Wlo,
              const float* __restrict__ bias, const float* __restrict__ res,
              float* __restrict__ out32, __half* __restrict__ outh,
              __half* __restrict__ ohi, __half* __restrict__ olo,
              int N, int Kd, int flags)
{
    __shared__ __align__(16) __half sA[2][PL][64 * 32];
    __shared__ __align__(16) __half sB[2][PL][64 * 32];

    const int tid  = threadIdx.x;
    const int m0   = blockIdx.x * 64;
    const int n0   = blockIdx.y * 64;
    const int lane = tid & 31;
    const int g    = lane >> 2;
    const int tig  = lane & 3;
    const int wm   = tid >> 6;
    const int wn   = (tid >> 5) & 1;

    const int lr0 = tid >> 2, lc = tid & 3, lr1 = lr0 + 32;
    const int so0 = (lr0 * 32 + ((lc ^ skey(lr0)) << 3)) * 2;
    const int so1 = (lr1 * 32 + ((lc ^ skey(lr1)) << 3)) * 2;

    uint32_t bA[2][PL], bB[2][PL];
#pragma unroll
    for (int bu = 0; bu < 2; bu++)
#pragma unroll
        for (int pl = 0; pl < PL; pl++) {
            bA[bu][pl] = (uint32_t)__cvta_generic_to_shared(sA[bu][pl]);
            bB[bu][pl] = (uint32_t)__cvta_generic_to_shared(sB[bu][pl]);
        }

    const int mat = lane >> 3, l8 = lane & 7;
    int offA[2][2], offB[2][2];
#pragma unroll
    for (int i = 0; i < 2; i++)
#pragma unroll
        for (int kh = 0; kh < 2; kh++) {
            int ra = wm * 32 + i * 16 + (mat & 1) * 8 + l8;
            int ca = kh * 2 + (mat >> 1);
            offA[i][kh] = (ra * 32 + ((ca ^ skey(ra)) << 3)) * 2;
            int rb = wn * 32 + i * 16 + (mat >> 1) * 8 + l8;
            int cb = kh * 2 + (mat & 1);
            offB[i][kh] = (rb * 32 + ((cb ^ skey(rb)) << 3)) * 2;
        }

    const __half* Ap[2] = { Ahi, Alo };
    const __half* Wp[2] = { Whi, Wlo };

    float acc[2][4][4];
#pragma unroll
    for (int t = 0; t < 2; t++)
#pragma unroll
        for (int j = 0; j < 4; j++)
#pragma unroll
            for (int e = 0; e < 4; e++) acc[t][j][e] = 0.0f;

#pragma unroll
    for (int pl = 0; pl < PL; pl++) {
        cpa16(bA[0][pl] + so0, Ap[pl] + (size_t)(m0 + lr0) * Kd + lc * 8);
        cpa16(bA[0][pl] + so1, Ap[pl] + (size_t)(m0 + lr1) * Kd + lc * 8);
        cpa16(bB[0][pl] + so0, Wp[pl] + (size_t)(n0 + lr0) * Kd + lc * 8);
        cpa16(bB[0][pl] + so1, Wp[pl] + (size_t)(n0 + lr1) * Kd + lc * 8);
    }
    cpa_commit();

    int buf = 0;
    for (int kc = 0; kc < Kd; kc += 32) {
        const bool more = (kc + 32) < Kd;
        if (more) {
            int nb = buf ^ 1;
            int ko = kc + 32;
#pragma unroll
            for (int pl = 0; pl < PL; pl++) {
                cpa16(bA[nb][pl] + so0, Ap[pl] + (size_t)(m0 + lr0) * Kd + ko + lc * 8);
                cpa16(bA[nb][pl] + so1, Ap[pl] + (size_t)(m0 + lr1) * Kd + ko + lc * 8);
                cpa16(bB[nb][pl] + so0, Wp[pl] + (size_t)(n0 + lr0) * Kd + ko + lc * 8);
                cpa16(bB[nb][pl] + so1, Wp[pl] + (size_t)(n0 + lr1) * Kd + ko + lc * 8);
            }
            cpa_commit();
            cpa_wait<1>();
        } else {
            cpa_wait<0>();
        }
        __syncthreads();

#pragma unroll
        for (int kh = 0; kh < 2; kh++) {
            uint32_t ah[2][4], bh[2][4];
            uint32_t al[2][4], bl[2][4];
#pragma unroll
            for (int i = 0; i < 2; i++) {
                ldsm4(ah[i], bA[buf][0] + offA[i][kh]);
                ldsm4(bh[i], bB[buf][0] + offB[i][kh]);
                if (PL == 2) {
                    ldsm4(al[i], bA[buf][1] + offA[i][kh]);
                    ldsm4(bl[i], bB[buf][1] + offB[i][kh]);
                }
            }
#pragma unroll
            for (int t = 0; t < 2; t++)
#pragma unroll
                for (int j = 0; j < 4; j++) {
                    const uint32_t* bhp = &bh[j >> 1][(j & 1) * 2];
                    mma16(acc[t][j], ah[t], bhp);
                    if (PL == 2) {
                        const uint32_t* blp = &bl[j >> 1][(j & 1) * 2];
                        mma16(acc[t][j], ah[t], blp);
                        mma16(acc[t][j], al[t], bhp);
                    }
                }
        }
        __syncthreads();
        buf ^= 1;
    }

#pragma unroll
    for (int t = 0; t < 2; t++) {
#pragma unroll
        for (int j = 0; j < 4; j++) {
            int row0 = m0 + wm * 32 + t * 16 + g;
            int col  = n0 + wn * 32 + j * 8 + 2 * tig;
            float2 bi = *(const float2*)(bias + col);
#pragma unroll
            for (int h2 = 0; h2 < 2; h2++) {
                int row = row0 + h2 * 8;
                float x0 = acc[t][j][h2 * 2 + 0] + bi.x;
                float x1 = acc[t][j][h2 * 2 + 1] + bi.y;
                size_t o = (size_t)row * N + col;
                if (flags & 2) {
                    float2 r2 = *(const float2*)(res + o);
                    x0 += r2.x; x1 += r2.y;
                }
                if (flags & 1) { x0 = fmaxf(x0, 0.0f); x1 = fmaxf(x1, 0.0f); }
                if (flags & 8)  *(float2*)(out32 + o) = make_float2(x0, x1);
                if (flags & 4)  *(__half2*)(outh + o) = __floats2half2_rn(x0, x1);
                if (flags & 16) {
                    __half h0, l0, h1, l1;
                    h2split(x0, h0, l0);
                    h2split(x1, h1, l1);
                    ohi[o] = h0; ohi[o + 1] = h1;
                    olo[o] = l0; olo[o + 1] = l1;
                }
            }
        }
    }
}

// ---------------- attention: one block per query, 128 threads ----------------
// No K/V smem staging: gather threads compute scores and P·V directly from
// registers; only p (padded) and a 2KB reduction buffer live in smem.
__global__ __launch_bounds__(128)
void attn_kernel(const int* __restrict__ kidx)
{
    __shared__ int   idx_s[KK];
    __shared__ float p_s[NH][PSS];
    __shared__ __align__(16) float red_s[4][C];

    const int n  = blockIdx.x;
    const int t  = threadIdx.x;
    const int rg = t >> 4;     // 0..7 (key subgroup)
    const int pp = t & 15;     // 0..15 (8-channel block)
    const int hh = pp >> 1;    // head owning channels pp*8..pp*8+7

    if (t < KK) idx_s[t] = kidx[n * KK + t];

    // q channels pp*8 .. pp*8+7 (coalesced float4 x2)
    float q8[8];
    {
        const float4* qp = (const float4*)(g_q + (size_t)n * C + pp * 8);
        float4 a = qp[0], b = qp[1];
        q8[0] = a.x; q8[1] = a.y; q8[2] = a.z; q8[3] = a.w;
        q8[4] = b.x; q8[5] = b.y; q8[6] = b.z; q8[7] = b.w;
    }
    __syncthreads();

    // ---- scores: key k = i*8+rg; pair-sum lanes (pp, pp^1) covers head hh ----
#pragma unroll
    for (int i = 0; i < 12; i++) {
        int k = i * 8 + rg;
        int v = idx_s[k];
        float partial = 0.0f;
        if (v >= 0) {
            uint4 k4 = *(const uint4*)(g_KVh + (size_t)v * 256 + pp * 8);
            const __half2* kh = (const __half2*)&k4;
#pragma unroll
            for (int j = 0; j < 4; j++) {
                float2 f = __half22float2(kh[j]);
                partial += q8[2 * j] * f.x + q8[2 * j + 1] * f.y;
            }
        }
        partial += __shfl_xor_sync(0xffffffffu, partial, 1);
        if ((pp & 1) == 0) p_s[hh][k] = partial * 0.25f;
    }
    __syncthreads();

    // ---- softmax per head: thread (h=rg, l16=pp) handles k = l16+16m ----
    {
        const int h = rg, l16 = pp;
        float sc[6]; int vm[6];
#pragma unroll
        for (int m = 0; m < 6; m++) {
            int k = l16 + m * 16;
            vm[m] = idx_s[k];
            sc[m] = p_s[h][k];
        }
        float mx = -1e30f;
#pragma unroll
        for (int m = 0; m < 6; m++)
            if (vm[m] >= 0) mx = fmaxf(mx, sc[m]);
#pragma unroll
        for (int o = 8; o; o >>= 1)
            mx = fmaxf(mx, __shfl_xor_sync(0xffffffffu, mx, o, 16));

        float p[6];
        float sum = 0.0f;
#pragma unroll
        for (int m = 0; m < 6; m++) {
            p[m] = (vm[m] >= 0) ? __expf(sc[m] - mx) : 0.0f;
            sum += p[m];
        }
#pragma unroll
        for (int o = 8; o; o >>= 1)
            sum += __shfl_xor_sync(0xffffffffu, sum, o, 16);
        const float inv = 1.0f / sum;
#pragma unroll
        for (int m = 0; m < 6; m++) p_s[h][l16 + m * 16] = p[m] * inv;
    }
    __syncthreads();

    // ---- ctx: same gather pattern on V half; accumulate in registers ----
    float facc[8];
#pragma unroll
    for (int j = 0; j < 8; j++) facc[j] = 0.0f;
#pragma unroll
    for (int i = 0; i < 12; i++) {
        int k = i * 8 + rg;
        int v = idx_s[k];
        if (v >= 0) {
            float pk = p_s[hh][k];
            uint4 v4 = *(const uint4*)(g_KVh + (size_t)v * 256 + 128 + pp * 8);
            const __half2* vh = (const __half2*)&v4;
#pragma unroll
            for (int j = 0; j < 4; j++) {
                float2 f = __half22float2(vh[j]);
                facc[2 * j + 0] += pk * f.x;
                facc[2 * j + 1] += pk * f.y;
            }
        }
    }
    // pair-reduce rg within warp (lanes differ in bit4), then 4-warp smem reduce
#pragma unroll
    for (int j = 0; j < 8; j++)
        facc[j] += __shfl_xor_sync(0xffffffffu, facc[j], 16);
    const int w = t >> 5;
    if ((t & 16) == 0) {
        *(float4*)&red_s[w][pp * 8]     = make_float4(facc[0], facc[1], facc[2], facc[3]);
        *(float4*)&red_s[w][pp * 8 + 4] = make_float4(facc[4], facc[5], facc[6], facc[7]);
    }
    __syncthreads();

    float acc = red_s[0][t] + red_s[1][t] + red_s[2][t] + red_s[3][t];

    __half oh, ol;
    h2split(acc, oh, ol);
    g_ctx_hi[n * C + t] = oh;
    g_ctx_lo[n * C + t] = ol;
}

// ---------------- host launch ----------------
extern "C" void kernel_launch(void* const* d_in, const int* in_sizes, int n_in,
                              void* d_out, int out_size)
{
    const float* vf   = (const float*)d_in[0];
    const float* vc   = (const float*)d_in[1];
    const float* qc   = (const float*)d_in[2];
    const int*   kidx = (const int*)  d_in[3];
    const float* n1g  = (const float*)d_in[4];
    const float* n1b  = (const float*)d_in[5];
    const float* qpw  = (const float*)d_in[6];
    const float* qpb  = (const float*)d_in[7];
    const float* kpw  = (const float*)d_in[8];
    const float* kpb  = (const float*)d_in[9];
    const float* inw  = (const float*)d_in[10];
    const float* inb  = (const float*)d_in[11];
    const float* outw = (const float*)d_in[12];
    const float* outb = (const float*)d_in[13];
    const float* n2g  = (const float*)d_in[14];
    const float* n2b  = (const float*)d_in[15];
    const float* l1w  = (const float*)d_in[16];
    const float* l1b  = (const float*)d_in[17];
    const float* l2w  = (const float*)d_in[18];
    const float* l2b  = (const float*)d_in[19];
    const float* fw   = (const float*)d_in[20];
    const float* fb   = (const float*)d_in[21];
    float* out = (float*)d_out;

    __half *p_kf_hi, *p_qf_hi, *p_ctx_hi, *p_ctx_lo;
    __half *p_hn_hi, *p_hn_lo, *p_a1_hi, *p_a1_lo, *p_x_hi, *p_x_lo;
    __half *p_w_hi, *p_w_lo, *p_KVh;
    float *p_q, *p_att;
    cudaGetSymbolAddress((void**)&p_kf_hi,  g_kf_hi);
    cudaGetSymbolAddress((void**)&p_KVh,    g_KVh);
    cudaGetSymbolAddress((void**)&p_qf_hi,  g_qf_hi);
    cudaGetSymbolAddress((void**)&p_q,      g_q);
    cudaGetSymbolAddress((void**)&p_ctx_hi, g_ctx_hi);
    cudaGetSymbolAddress((void**)&p_ctx_lo, g_ctx_lo);
    cudaGetSymbolAddress((void**)&p_att,    g_att);
    cudaGetSymbolAddress((void**)&p_hn_hi,  g_hn_hi);
    cudaGetSymbolAddress((void**)&p_hn_lo,  g_hn_lo);
    cudaGetSymbolAddress((void**)&p_a1_hi,  g_a1_hi);
    cudaGetSymbolAddress((void**)&p_a1_lo,  g_a1_lo);
    cudaGetSymbolAddress((void**)&p_x_hi,   g_x_hi);
    cudaGetSymbolAddress((void**)&p_x_lo,   g_x_lo);
    cudaGetSymbolAddress((void**)&p_w_hi,   g_w_hi);
    cudaGetSymbolAddress((void**)&p_w_lo,   g_w_lo);

    // 0) fused prep: weight split + kf + qfeat
    prep_kernel<<<PB_TOT, 256>>>(inw, outw, l1w, l2w, fw,
                                 vf, vc, n1g, n1b, kpw, kpb,
                                 qc, qpw, qpb);

    // 1) per-voxel K|V projection (fp16, 128x128 tile, 256 thr) -> fp16
    mma_kv<<<dim3((NVOX + 127) / 128, 2), 256>>>(
        p_kf_hi, p_w_hi + W_INW + 128 * 128, inb + 128, p_KVh,
        NVOX, 256, 128);

    // 2) q projection (single-pass fp16) -> fp32
    mma_gemm<1><<<dim3(NQ / 64, 2), 128>>>(
        p_qf_hi, nullptr, p_w_hi + W_INW, nullptr,
        inb, nullptr, p_q, nullptr, nullptr, nullptr, 128, 128, 8);

    // 3) sparse attention -> ctx hi/lo
    attn_kernel<<<NQ, 128>>>(kidx);

    // 4) output projection (3-pass) -> attend fp32
    mma_gemm<2><<<dim3(NQ / 64, 2), 128>>>(
        p_ctx_hi, p_ctx_lo, p_w_hi + W_OUTW, p_w_lo + W_OUTW,
        outb, nullptr, p_att, nullptr, nullptr, nullptr, 128, 128, 8);

    // 5) norm2 -> hn hi/lo
    ln_kernel<<<NQ / 8, 256>>>(p_att, n2g, n2b);

    // 6) FFN up (relu, 3-pass) -> a1 hi/lo
    mma_gemm<2><<<dim3(NQ / 64, 4), 128>>>(
        p_hn_hi, p_hn_lo, p_w_hi + W_L1W, p_w_lo + W_L1W,
        l1b, nullptr, nullptr, nullptr, p_a1_hi, p_a1_lo, 256, 128, 16 | 1);

    // 7) FFN down + residual(attend) (3-pass) -> x hi/lo
    mma_gemm<2><<<dim3(NQ / 64, 2), 128>>>(
        p_a1_hi, p_a1_lo, p_w_hi + W_L2W, p_w_lo + W_L2W,
        l2b, p_att, nullptr, nullptr, p_x_hi, p_x_lo, 128, 256, 16 | 2);

    // 8) final projection + relu (3-pass) -> output fp32
    mma_gemm<2><<<dim3(NQ / 64, 2), 128>>>(
        p_x_hi, p_x_lo, p_w_hi + W_FINW, p_w_lo + W_FINW,
        fb, nullptr, out, nullptr, nullptr, nullptr, 128, 128, 8 | 1);
}

// round 15
// speedup vs baseline: 1.7093x; 1.2850x over previous
#include <cuda_runtime.h>
#include <cuda_fp16.h>
#include <math.h>
#include <stdint.h>

#define NVOX 40000
#define NQ   8192
#define KK   96
#define C    128
#define FF   256
#define NH   8
#define PSS  100

// weight buffer offsets (halfs)
#define W_INW  0
#define W_OUTW 49152
#define W_L1W  65536
#define W_L2W  98304
#define W_FINW 131072
#define W_TOT  147456

// prep kernel block ranges
#define PB_W   576
#define PB_KF  5000
#define PB_QF  4096
#define PB_TOT (PB_W + PB_KF + PB_QF)

// ---------------- scratch (device globals; no allocation) ----------------
__device__ __half g_w[W_TOT];
__device__ __half g_kf[NVOX * C];
__device__ __half g_KVh[NVOX * 2 * C];
__device__ __half g_qf[NQ * C];
__device__ __half g_q16[NQ * C];
__device__ __half g_ctx[NQ * C];
__device__ float  g_att[NQ * C];
__device__ __half g_hn[NQ * C];
__device__ __half g_a1[NQ * FF];
__device__ __half g_x[NQ * C];

// ---------------- helpers ----------------
__device__ __forceinline__ int skey(int r) { return (r ^ (r >> 2)) & 3; }

__device__ __forceinline__ void ldsm4(uint32_t* r, uint32_t addr) {
    asm volatile("ldmatrix.sync.aligned.m8n8.x4.shared.b16 {%0,%1,%2,%3}, [%4];"
                 : "=r"(r[0]), "=r"(r[1]), "=r"(r[2]), "=r"(r[3]) : "r"(addr));
}

__device__ __forceinline__ void mma16(float* d, const uint32_t* a, const uint32_t* b) {
    asm volatile(
        "mma.sync.aligned.m16n8k16.row.col.f32.f16.f16.f32 "
        "{%0,%1,%2,%3}, {%4,%5,%6,%7}, {%8,%9}, {%0,%1,%2,%3};"
        : "+f"(d[0]), "+f"(d[1]), "+f"(d[2]), "+f"(d[3])
        : "r"(a[0]), "r"(a[1]), "r"(a[2]), "r"(a[3]), "r"(b[0]), "r"(b[1]));
}

__device__ __forceinline__ void cpa16(uint32_t s, const void* g) {
    asm volatile("cp.async.cg.shared.global [%0], [%1], 16;" :: "r"(s), "l"(g));
}
__device__ __forceinline__ void cpa_commit() {
    asm volatile("cp.async.commit_group;");
}
template <int N>
__device__ __forceinline__ void cpa_wait() {
    asm volatile("cp.async.wait_group %0;" :: "n"(N));
}

// ---------------- fused prep: weight fp16 + kf (LN+pos) + qfeat -----------
__global__ __launch_bounds__(256)
void prep_kernel(const float* __restrict__ s0, const float* __restrict__ s1,
                 const float* __restrict__ s2, const float* __restrict__ s3,
                 const float* __restrict__ s4,
                 const float* __restrict__ vf, const float* __restrict__ vc,
                 const float* __restrict__ g1, const float* __restrict__ b1,
                 const float* __restrict__ kpw, const float* __restrict__ kpb,
                 const float* __restrict__ qc, const float* __restrict__ qpw,
                 const float* __restrict__ qpb)
{
    const int b = blockIdx.x;
    if (b < PB_W) {
        int i = b * 256 + threadIdx.x;
        const float* s; int off;
        if      (i < W_OUTW) { s = s0; off = W_INW;  }
        else if (i < W_L1W)  { s = s1; off = W_OUTW; }
        else if (i < W_L2W)  { s = s2; off = W_L1W;  }
        else if (i < W_FINW) { s = s3; off = W_L2W;  }
        else                 { s = s4; off = W_FINW; }
        g_w[i] = __float2half(s[i - off]);
    } else if (b < PB_W + PB_KF) {
        int v    = (b - PB_W) * 8 + (threadIdx.x >> 5);
        int lane = threadIdx.x & 31;
        if (v >= NVOX) return;

        float4 x = ((const float4*)(vf + (size_t)v * C))[lane];
        float s = x.x + x.y + x.z + x.w;
        float q = x.x * x.x + x.y * x.y + x.z * x.z + x.w * x.w;
#pragma unroll
        for (int o = 16; o; o >>= 1) {
            s += __shfl_xor_sync(0xffffffffu, s, o);
            q += __shfl_xor_sync(0xffffffffu, q, o);
        }
        float m   = s * (1.0f / 128.0f);
        float var = q * (1.0f / 128.0f) - m * m;
        float r   = rsqrtf(var + 1e-5f);

        float cx = vc[v * 3 + 0], cy = vc[v * 3 + 1], cz = vc[v * 3 + 2];

        const float* xv = &x.x;
#pragma unroll
        for (int j = 0; j < 4; j++) {
            int c = lane * 4 + j;
            float y  = (xv[j] - m) * r * g1[c] + b1[c];
            float kp = fmaxf(kpw[c * 3 + 0] * cx + kpw[c * 3 + 1] * cy +
                             kpw[c * 3 + 2] * cz + kpb[c], 0.0f);
            g_kf[v * C + c] = __float2half(y + kp);
        }
    } else {
        int t = (b - PB_W - PB_KF) * 256 + threadIdx.x;
        int n = t >> 7, c = t & 127;
        float x = qc[n * 3 + 0], y = qc[n * 3 + 1], z = qc[n * 3 + 2];
        float v = fmaxf(qpw[c * 3 + 0] * x + qpw[c * 3 + 1] * y +
                        qpw[c * 3 + 2] * z + qpb[c], 0.0f);
        g_qf[t] = __float2half(v);
    }
}

// ---------------- row LayerNorm (norm2) -> fp16 ----------------
__global__ void ln_kernel(const float* __restrict__ in,
                          const float* __restrict__ g,
                          const float* __restrict__ b)
{
    int r    = blockIdx.x * 8 + (threadIdx.x >> 5);
    int lane = threadIdx.x & 31;

    float4 x = ((const float4*)(in + (size_t)r * C))[lane];
    float s = x.x + x.y + x.z + x.w;
    float q = x.x * x.x + x.y * x.y + x.z * x.z + x.w * x.w;
#pragma unroll
    for (int o = 16; o; o >>= 1) {
        s += __shfl_xor_sync(0xffffffffu, s, o);
        q += __shfl_xor_sync(0xffffffffu, q, o);
    }
    float m   = s * (1.0f / 128.0f);
    float var = q * (1.0f / 128.0f) - m * m;
    float rs  = rsqrtf(var + 1e-5f);

    const float* xv = &x.x;
#pragma unroll
    for (int j = 0; j < 4; j++) {
        int c = lane * 4 + j;
        g_hn[r * C + c] = __float2half((xv[j] - m) * rs * g[c] + b[c]);
    }
}

// ---------------- KV GEMM: 256 threads, CTA 128x128, fp16 single-pass -------
__global__ __launch_bounds__(256, 2)
void mma_kv(const __half* __restrict__ A, const __half* __restrict__ W,
            const float* __restrict__ bias, __half* __restrict__ outh,
            int M, int N, int Kd)
{
    __shared__ __align__(16) __half sA[2][128 * 32];
    __shared__ __align__(16) __half sB[2][128 * 32];

    const int tid  = threadIdx.x;
    const int m0   = blockIdx.x * 128;
    const int n0   = blockIdx.y * 128;
    const int lane = tid & 31;
    const int g    = lane >> 2;
    const int tig  = lane & 3;
    const int warp = tid >> 5;
    const int wm   = warp >> 1;
    const int wn   = warp & 1;

    const int lr = tid >> 2, lc = tid & 3;
    int so[2];
    bool okA[2];
#pragma unroll
    for (int i = 0; i < 2; i++) {
        int r = lr + 64 * i;
        so[i]  = (r * 32 + ((lc ^ skey(r)) << 3)) * 2;
        okA[i] = (m0 + r) < M;
    }

    uint32_t bA[2], bB[2];
#pragma unroll
    for (int bu = 0; bu < 2; bu++) {
        bA[bu] = (uint32_t)__cvta_generic_to_shared(sA[bu]);
        bB[bu] = (uint32_t)__cvta_generic_to_shared(sB[bu]);
    }

    const int mat = lane >> 3, l8 = lane & 7;
    int offA[2][2], offB[4][2];
#pragma unroll
    for (int kh = 0; kh < 2; kh++) {
#pragma unroll
        for (int i = 0; i < 2; i++) {
            int ra = wm * 32 + i * 16 + (mat & 1) * 8 + l8;
            int ca = kh * 2 + (mat >> 1);
            offA[i][kh] = (ra * 32 + ((ca ^ skey(ra)) << 3)) * 2;
        }
#pragma unroll
        for (int i = 0; i < 4; i++) {
            int rb = wn * 64 + i * 16 + (mat >> 1) * 8 + l8;
            int cb = kh * 2 + (mat & 1);
            offB[i][kh] = (rb * 32 + ((cb ^ skey(rb)) << 3)) * 2;
        }
    }

    float acc[2][8][4];
#pragma unroll
    for (int t = 0; t < 2; t++)
#pragma unroll
        for (int j = 0; j < 8; j++)
#pragma unroll
            for (int e = 0; e < 4; e++) acc[t][j][e] = 0.0f;

#pragma unroll
    for (int i = 0; i < 2; i++) {
        if (okA[i]) cpa16(bA[0] + so[i], A + (size_t)(m0 + lr + 64 * i) * Kd + lc * 8);
        cpa16(bB[0] + so[i], W + (size_t)(n0 + lr + 64 * i) * Kd + lc * 8);
    }
    cpa_commit();

    int buf = 0;
    for (int kc = 0; kc < Kd; kc += 32) {
        const bool more = (kc + 32) < Kd;
        if (more) {
            int nb = buf ^ 1;
            int ko = kc + 32;
#pragma unroll
            for (int i = 0; i < 2; i++) {
                if (okA[i]) cpa16(bA[nb] + so[i], A + (size_t)(m0 + lr + 64 * i) * Kd + ko + lc * 8);
                cpa16(bB[nb] + so[i], W + (size_t)(n0 + lr + 64 * i) * Kd + ko + lc * 8);
            }
            cpa_commit();
            cpa_wait<1>();
        } else {
            cpa_wait<0>();
        }
        __syncthreads();

#pragma unroll
        for (int kh = 0; kh < 2; kh++) {
            uint32_t ah[2][4], bh[4][4];
#pragma unroll
            for (int i = 0; i < 2; i++) ldsm4(ah[i], bA[buf] + offA[i][kh]);
#pragma unroll
            for (int i = 0; i < 4; i++) ldsm4(bh[i], bB[buf] + offB[i][kh]);
#pragma unroll
            for (int t = 0; t < 2; t++)
#pragma unroll
                for (int j = 0; j < 8; j++)
                    mma16(acc[t][j], ah[t], &bh[j >> 1][(j & 1) * 2]);
        }
        __syncthreads();
        buf ^= 1;
    }

#pragma unroll
    for (int t = 0; t < 2; t++) {
#pragma unroll
        for (int j = 0; j < 8; j++) {
            int row0 = m0 + wm * 32 + t * 16 + g;
            int col  = n0 + wn * 64 + j * 8 + 2 * tig;
            float2 bi = *(const float2*)(bias + col);
#pragma unroll
            for (int h2 = 0; h2 < 2; h2++) {
                int row = row0 + h2 * 8;
                if (row >= M) continue;
                float x0 = acc[t][j][h2 * 2 + 0] + bi.x;
                float x1 = acc[t][j][h2 * 2 + 1] + bi.y;
                *(__half2*)(outh + (size_t)row * N + col) = __floats2half2_rn(x0, x1);
            }
        }
    }
}

// ---------------- tensor-core GEMM (single-pass fp16) ----------------------
// out[M,N] = A[M,Kd] @ W[N,Kd]^T + bias (+res)(relu)
// CTA 64x64, 4 warps of 32x32, BK=32, cp.async double-buffered.
// flags: 1=relu, 2=res, 4=half out, 8=f32 out
__global__ __launch_bounds__(128)
void mma_gemm(const __half* __restrict__ A, const __half* __restrict__ W,
              const float* __restrict__ bias, const float* __restrict__ res,
              float* __restrict__ out32, __half* __restrict__ outh,
              int N, int Kd, int flags)
{
    __shared__ __align__(16) __half sA[2][64 * 32];
    __shared__ __align__(16) __half sB[2][64 * 32];

    const int tid  = threadIdx.x;
    const int m0   = blockIdx.x * 64;
    const int n0   = blockIdx.y * 64;
    const int lane = tid & 31;
    const int g    = lane >> 2;
    const int tig  = lane & 3;
    const int wm   = tid >> 6;
    const int wn   = (tid >> 5) & 1;

    const int lr0 = tid >> 2, lc = tid & 3, lr1 = lr0 + 32;
    const int so0 = (lr0 * 32 + ((lc ^ skey(lr0)) << 3)) * 2;
    const int so1 = (lr1 * 32 + ((lc ^ skey(lr1)) << 3)) * 2;

    uint32_t bA[2], bB[2];
#pragma unroll
    for (int bu = 0; bu < 2; bu++) {
        bA[bu] = (uint32_t)__cvta_generic_to_shared(sA[bu]);
        bB[bu] = (uint32_t)__cvta_generic_to_shared(sB[bu]);
    }

    const int mat = lane >> 3, l8 = lane & 7;
    int offA[2][2], offB[2][2];
#pragma unroll
    for (int i = 0; i < 2; i++)
#pragma unroll
        for (int kh = 0; kh < 2; kh++) {
            int ra = wm * 32 + i * 16 + (mat & 1) * 8 + l8;
            int ca = kh * 2 + (mat >> 1);
            offA[i][kh] = (ra * 32 + ((ca ^ skey(ra)) << 3)) * 2;
            int rb = wn * 32 + i * 16 + (mat >> 1) * 8 + l8;
            int cb = kh * 2 + (mat & 1);
            offB[i][kh] = (rb * 32 + ((cb ^ skey(rb)) << 3)) * 2;
        }

    float acc[2][4][4];
#pragma unroll
    for (int t = 0; t < 2; t++)
#pragma unroll
        for (int j = 0; j < 4; j++)
#pragma unroll
            for (int e = 0; e < 4; e++) acc[t][j][e] = 0.0f;

    cpa16(bA[0] + so0, A + (size_t)(m0 + lr0) * Kd + lc * 8);
    cpa16(bA[0] + so1, A + (size_t)(m0 + lr1) * Kd + lc * 8);
    cpa16(bB[0] + so0, W + (size_t)(n0 + lr0) * Kd + lc * 8);
    cpa16(bB[0] + so1, W + (size_t)(n0 + lr1) * Kd + lc * 8);
    cpa_commit();

    int buf = 0;
    for (int kc = 0; kc < Kd; kc += 32) {
        const bool more = (kc + 32) < Kd;
        if (more) {
            int nb = buf ^ 1;
            int ko = kc + 32;
            cpa16(bA[nb] + so0, A + (size_t)(m0 + lr0) * Kd + ko + lc * 8);
            cpa16(bA[nb] + so1, A + (size_t)(m0 + lr1) * Kd + ko + lc * 8);
            cpa16(bB[nb] + so0, W + (size_t)(n0 + lr0) * Kd + ko + lc * 8);
            cpa16(bB[nb] + so1, W + (size_t)(n0 + lr1) * Kd + ko + lc * 8);
            cpa_commit();
            cpa_wait<1>();
        } else {
            cpa_wait<0>();
        }
        __syncthreads();

#pragma unroll
        for (int kh = 0; kh < 2; kh++) {
            uint32_t ah[2][4], bh[2][4];
#pragma unroll
            for (int i = 0; i < 2; i++) {
                ldsm4(ah[i], bA[buf] + offA[i][kh]);
                ldsm4(bh[i], bB[buf] + offB[i][kh]);
            }
#pragma unroll
            for (int t = 0; t < 2; t++)
#pragma unroll
                for (int j = 0; j < 4; j++)
                    mma16(acc[t][j], ah[t], &bh[j >> 1][(j & 1) * 2]);
        }
        __syncthreads();
        buf ^= 1;
    }

#pragma unroll
    for (int t = 0; t < 2; t++) {
#pragma unroll
        for (int j = 0; j < 4; j++) {
            int row0 = m0 + wm * 32 + t * 16 + g;
            int col  = n0 + wn * 32 + j * 8 + 2 * tig;
            float2 bi = *(const float2*)(bias + col);
#pragma unroll
            for (int h2 = 0; h2 < 2; h2++) {
                int row = row0 + h2 * 8;
                float x0 = acc[t][j][h2 * 2 + 0] + bi.x;
                float x1 = acc[t][j][h2 * 2 + 1] + bi.y;
                size_t o = (size_t)row * N + col;
                if (flags & 2) {
                    float2 r2 = *(const float2*)(res + o);
                    x0 += r2.x; x1 += r2.y;
                }
                if (flags & 1) { x0 = fmaxf(x0, 0.0f); x1 = fmaxf(x1, 0.0f); }
                if (flags & 8)  *(float2*)(out32 + o) = make_float2(x0, x1);
                if (flags & 4)  *(__half2*)(outh + o) = __floats2half2_rn(x0, x1);
            }
        }
    }
}

// ---------------- attention: one block per query, 128 threads ----------------
// Register-direct gather; fp16 HFMA2 scores; fp32 ctx accumulation.
__global__ __launch_bounds__(128)
void attn_kernel(const int* __restrict__ kidx)
{
    __shared__ int   idx_s[KK];
    __shared__ float p_s[NH][PSS];
    __shared__ __align__(16) float red_s[4][C];

    const int n  = blockIdx.x;
    const int t  = threadIdx.x;
    const int rg = t >> 4;     // key subgroup
    const int pp = t & 15;     // 8-channel block
    const int hh = pp >> 1;    // head owning channels pp*8..pp*8+7

    if (t < KK) idx_s[t] = kidx[n * KK + t];

    // q channels pp*8..pp*8+7 as 4 half2
    __half2 q2[4];
    {
        uint4 qv = *(const uint4*)(g_q16 + (size_t)n * C + pp * 8);
        const __half2* qh = (const __half2*)&qv;
        q2[0] = qh[0]; q2[1] = qh[1]; q2[2] = qh[2]; q2[3] = qh[3];
    }
    __syncthreads();

    // ---- scores (fp16 dot): key k = i*8+rg; pair-sum lanes (pp, pp^1) ----
#pragma unroll
    for (int i = 0; i < 12; i++) {
        int k = i * 8 + rg;
        int v = idx_s[k];
        float partial = 0.0f;
        if (v >= 0) {
            uint4 k4 = *(const uint4*)(g_KVh + (size_t)v * 256 + pp * 8);
            const __half2* kh = (const __half2*)&k4;
            __half2 a2 = __hmul2(q2[0], kh[0]);
            a2 = __hfma2(q2[1], kh[1], a2);
            a2 = __hfma2(q2[2], kh[2], a2);
            a2 = __hfma2(q2[3], kh[3], a2);
            partial = __low2float(a2) + __high2float(a2);
        }
        partial += __shfl_xor_sync(0xffffffffu, partial, 1);
        if ((pp & 1) == 0) p_s[hh][k] = partial * 0.25f;
    }
    __syncthreads();

    // ---- softmax per head: thread (h=rg, l16=pp) handles k = l16+16m ----
    {
        const int h = rg, l16 = pp;
        float sc[6]; int vm[6];
#pragma unroll
        for (int m = 0; m < 6; m++) {
            int k = l16 + m * 16;
            vm[m] = idx_s[k];
            sc[m] = p_s[h][k];
        }
        float mx = -1e30f;
#pragma unroll
        for (int m = 0; m < 6; m++)
            if (vm[m] >= 0) mx = fmaxf(mx, sc[m]);
#pragma unroll
        for (int o = 8; o; o >>= 1)
            mx = fmaxf(mx, __shfl_xor_sync(0xffffffffu, mx, o, 16));

        float p[6];
        float sum = 0.0f;
#pragma unroll
        for (int m = 0; m < 6; m++) {
            p[m] = (vm[m] >= 0) ? __expf(sc[m] - mx) : 0.0f;
            sum += p[m];
        }
#pragma unroll
        for (int o = 8; o; o >>= 1)
            sum += __shfl_xor_sync(0xffffffffu, sum, o, 16);
        const float inv = 1.0f / sum;
#pragma unroll
        for (int m = 0; m < 6; m++) p_s[h][l16 + m * 16] = p[m] * inv;
    }
    __syncthreads();

    // ---- ctx: register accumulation (fp32) ----
    float facc[8];
#pragma unroll
    for (int j = 0; j < 8; j++) facc[j] = 0.0f;
#pragma unroll
    for (int i = 0; i < 12; i++) {
        int k = i * 8 + rg;
        int v = idx_s[k];
        if (v >= 0) {
            float pk = p_s[hh][k];
            uint4 v4 = *(const uint4*)(g_KVh + (size_t)v * 256 + 128 + pp * 8);
            const __half2* vh = (const __half2*)&v4;
#pragma unroll
            for (int j = 0; j < 4; j++) {
                float2 f = __half22float2(vh[j]);
                facc[2 * j + 0] += pk * f.x;
                facc[2 * j + 1] += pk * f.y;
            }
        }
    }
#pragma unroll
    for (int j = 0; j < 8; j++)
        facc[j] += __shfl_xor_sync(0xffffffffu, facc[j], 16);
    const int w = t >> 5;
    if ((t & 16) == 0) {
        *(float4*)&red_s[w][pp * 8]     = make_float4(facc[0], facc[1], facc[2], facc[3]);
        *(float4*)&red_s[w][pp * 8 + 4] = make_float4(facc[4], facc[5], facc[6], facc[7]);
    }
    __syncthreads();

    float acc = red_s[0][t] + red_s[1][t] + red_s[2][t] + red_s[3][t];
    g_ctx[n * C + t] = __float2half(acc);
}

// ---------------- host launch ----------------
extern "C" void kernel_launch(void* const* d_in, const int* in_sizes, int n_in,
                              void* d_out, int out_size)
{
    const float* vf   = (const float*)d_in[0];
    const float* vc   = (const float*)d_in[1];
    const float* qc   = (const float*)d_in[2];
    const int*   kidx = (const int*)  d_in[3];
    const float* n1g  = (const float*)d_in[4];
    const float* n1b  = (const float*)d_in[5];
    const float* qpw  = (const float*)d_in[6];
    const float* qpb  = (const float*)d_in[7];
    const float* kpw  = (const float*)d_in[8];
    const float* kpb  = (const float*)d_in[9];
    const float* inw  = (const float*)d_in[10];
    const float* inb  = (const float*)d_in[11];
    const float* outw = (const float*)d_in[12];
    const float* outb = (const float*)d_in[13];
    const float* n2g  = (const float*)d_in[14];
    const float* n2b  = (const float*)d_in[15];
    const float* l1w  = (const float*)d_in[16];
    const float* l1b  = (const float*)d_in[17];
    const float* l2w  = (const float*)d_in[18];
    const float* l2b  = (const float*)d_in[19];
    const float* fw   = (const float*)d_in[20];
    const float* fb   = (const float*)d_in[21];
    float* out = (float*)d_out;

    __half *p_kf, *p_qf, *p_q16, *p_ctx, *p_hn, *p_a1, *p_x, *p_w, *p_KVh;
    float *p_att;
    cudaGetSymbolAddress((void**)&p_kf,  g_kf);
    cudaGetSymbolAddress((void**)&p_KVh, g_KVh);
    cudaGetSymbolAddress((void**)&p_qf,  g_qf);
    cudaGetSymbolAddress((void**)&p_q16, g_q16);
    cudaGetSymbolAddress((void**)&p_ctx, g_ctx);
    cudaGetSymbolAddress((void**)&p_att, g_att);
    cudaGetSymbolAddress((void**)&p_hn,  g_hn);
    cudaGetSymbolAddress((void**)&p_a1,  g_a1);
    cudaGetSymbolAddress((void**)&p_x,   g_x);
    cudaGetSymbolAddress((void**)&p_w,   g_w);

    // 0) fused prep: weight fp16 + kf + qfeat
    prep_kernel<<<PB_TOT, 256>>>(inw, outw, l1w, l2w, fw,
                                 vf, vc, n1g, n1b, kpw, kpb,
                                 qc, qpw, qpb);

    // 1) per-voxel K|V projection -> fp16 [NVOX,256]
    mma_kv<<<dim3((NVOX + 127) / 128, 2), 256>>>(
        p_kf, p_w + W_INW + 128 * 128, inb + 128, p_KVh, NVOX, 256, 128);

    // 2) q projection -> fp16
    mma_gemm<<<dim3(NQ / 64, 2), 128>>>(
        p_qf, p_w + W_INW, inb, nullptr, nullptr, p_q16, 128, 128, 4);

    // 3) sparse attention -> ctx fp16
    attn_kernel<<<NQ, 128>>>(kidx);

    // 4) output projection -> attend fp32
    mma_gemm<<<dim3(NQ / 64, 2), 128>>>(
        p_ctx, p_w + W_OUTW, outb, nullptr, p_att, nullptr, 128, 128, 8);

    // 5) norm2 -> hn fp16
    ln_kernel<<<NQ / 8, 256>>>(p_att, n2g, n2b);

    // 6) FFN up (relu) -> a1 fp16
    mma_gemm<<<dim3(NQ / 64, 4), 128>>>(
        p_hn, p_w + W_L1W, l1b, nullptr, nullptr, p_a1, 256, 128, 4 | 1);

    // 7) FFN down + residual(attend) -> x fp16
    mma_gemm<<<dim3(NQ / 64, 2), 128>>>(
        p_a1, p_w + W_L2W, l2b, p_att, nullptr, p_x, 128, 256, 4 | 2);

    // 8) final projection + relu -> output fp32
    mma_gemm<<<dim3(NQ / 64, 2), 128>>>(
        p_x, p_w + W_FINW, fb, nullptr, out, nullptr, 128, 128, 8 | 1);
}